// round 15
// baseline (speedup 1.0000x reference)
#include <cuda_runtime.h>
#include <cuda_fp16.h>
#include <cstdint>

#define NU 100000
#define NI 50000
#define NE 1600000
#define D  128

// ---------------- scratch (device globals) ----------------------------------
__device__ int g_h_fs[NU];
__device__ int g_h_fd[NU];
__device__ int g_h_rs[NU];
__device__ int g_h_rd[NI];
__device__ int g_h_vs[NI];
__device__ int g_h_vd[NU];

__device__ float g_inv_fs[NU];
__device__ float g_inv_fd[NU];
__device__ float g_inv_rs[NU];
__device__ float g_inv_rd[NI];
__device__ float g_inv_vs[NI];
__device__ float g_inv_vd[NU];

__device__ int   g_off_c[NU + 1];
__device__ int   g_off_r[NI + 1];
__device__ int   g_pos_c[NU];
__device__ int   g_pos_r[NI];
__device__ int2  g_ec[2 * NE];
__device__ int2  g_er[NE];
__device__ int   g_bsum[2][1024];

__device__ __half g_hc1[(size_t)(NU + NI) * D];
__device__ __half g_hc2[(size_t)(NU + NI) * D];
__device__ __half g_hu2 [(size_t)NU * D];
__device__ __half g_hu2b[(size_t)NU * D];
__device__ float  g_u  [(size_t)NU * D];
__device__ float  g_it [(size_t)NI * D];

// ---------------- setup kernels ----------------------------------------------

__global__ void k_zero_hists() {
    int i = blockIdx.x * blockDim.x + threadIdx.x;
    if (i < NU) { g_h_fs[i] = 0; g_h_fd[i] = 0; g_h_rs[i] = 0; g_h_vd[i] = 0; }
    if (i < NI) { g_h_rd[i] = 0; g_h_vs[i] = 0; }
}

__global__ void k_hist3(const int* __restrict__ fs, const int* __restrict__ fd,
                        const int* __restrict__ rs, const int* __restrict__ rd,
                        const int* __restrict__ vs, const int* __restrict__ vd) {
    int e = blockIdx.x * blockDim.x + threadIdx.x;
    if (e >= NE) return;
    if (blockIdx.y == 0) {
        atomicAdd(&g_h_fs[fs[e]], 1);
        atomicAdd(&g_h_fd[fd[e]], 1);
    } else if (blockIdx.y == 1) {
        atomicAdd(&g_h_rs[rs[e]], 1);
        atomicAdd(&g_h_rd[rd[e]], 1);
    } else {
        atomicAdd(&g_h_vs[vs[e]], 1);
        atomicAdd(&g_h_vd[vd[e]], 1);
    }
}

__device__ __forceinline__ float invsq(int x) {
    return x > 0 ? rsqrtf((float)x) : 0.f;
}

__global__ void k_inv_all() {
    int i = blockIdx.x * blockDim.x + threadIdx.x;
    if (i < NU) {
        g_inv_fs[i] = invsq(g_h_fs[i]);
        g_inv_fd[i] = invsq(g_h_fd[i]);
        g_inv_rs[i] = invsq(g_h_rs[i]);
        g_inv_vd[i] = invsq(g_h_vd[i]);
    }
    if (i < NI) {
        g_inv_rd[i] = invsq(g_h_rd[i]);
        g_inv_vs[i] = invsq(g_h_vs[i]);
    }
}

__global__ void k_scan1() {
    __shared__ int s[1024];
    int tid = threadIdx.x;
    int i = blockIdx.x * 1024 + tid;
    int v;
    int* outp; int n;
    if (blockIdx.y == 0) {
        n = NU; outp = g_off_c;
        v = (i < n) ? (g_h_fd[i] + g_h_vd[i]) : 0;
    } else {
        n = NI; outp = g_off_r;
        v = (i < n) ? g_h_rd[i] : 0;
    }
    s[tid] = v;
    __syncthreads();
#pragma unroll
    for (int o = 1; o < 1024; o <<= 1) {
        int t = (tid >= o) ? s[tid - o] : 0;
        __syncthreads();
        s[tid] += t;
        __syncthreads();
    }
    if (i < n) outp[i] = s[tid] - v;
    if (tid == 1023) g_bsum[blockIdx.y][blockIdx.x] = s[1023];
}

__global__ void k_scan2() {
    __shared__ int s[1024];
    int nb = (blockIdx.x == 1) ? (NI + 1023) / 1024 : (NU + 1023) / 1024;
    int tid = threadIdx.x;
    int v = (tid < nb) ? g_bsum[blockIdx.x][tid] : 0;
    s[tid] = v;
    __syncthreads();
#pragma unroll
    for (int o = 1; o < 1024; o <<= 1) {
        int t = (tid >= o) ? s[tid - o] : 0;
        __syncthreads();
        s[tid] += t;
        __syncthreads();
    }
    if (tid < nb) g_bsum[blockIdx.x][tid] = s[tid] - v;
}

__global__ void k_scan3() {
    int* outp; int* pos; int n; int total;
    if (blockIdx.y == 0) { outp = g_off_c; pos = g_pos_c; n = NU; total = 2 * NE; }
    else                 { outp = g_off_r; pos = g_pos_r; n = NI; total = NE; }
    int i = blockIdx.x * blockDim.x + threadIdx.x;
    if (i < n) {
        int v = outp[i] + g_bsum[blockIdx.y][i >> 10];
        outp[i] = v;
        pos[i] = v;
    } else if (i == n) {
        outp[n] = total;
    }
}

__global__ void k_fill3(const int* __restrict__ fs, const int* __restrict__ fd,
                        const int* __restrict__ rs, const int* __restrict__ rd,
                        const int* __restrict__ vs, const int* __restrict__ vd) {
    int e = blockIdx.x * blockDim.x + threadIdx.x;
    if (e >= NE) return;
    if (blockIdx.y == 0) {
        int s = fs[e], d = fd[e];
        float w = 0.5f * g_inv_fs[s] * g_inv_fd[d];
        int p = atomicAdd(&g_pos_c[d], 1);
        g_ec[p] = make_int2(s, __float_as_int(w));
    } else if (blockIdx.y == 1) {
        int s = rs[e], d = rd[e];
        float w = g_inv_rs[s] * g_inv_rd[d];
        int p = atomicAdd(&g_pos_r[d], 1);
        g_er[p] = make_int2(s, __float_as_int(w));
    } else {
        int s = vs[e], d = vd[e];
        float w = 0.5f * g_inv_vs[s] * g_inv_vd[d];
        int p = atomicAdd(&g_pos_c[d], 1);
        g_ec[p] = make_int2(NU + s, __float_as_int(w));
    }
}

// ---------------- GEMM via mma.sync (HMMA), split-fp16, fp32 accumulate -------
// C[n,128](fp16) = A[n,128](fp32) @ W[128,128](fp32).
// A, W^T staged as fp16 hi/lo in smem (KS=136 stride: frag LDS conflict-free).
// 3 passes: Ah*Wh + Ah*Wl + Al*Wh. 8 warps x 16 rows = 128-row tile.

#define KS 136
#define GEMM_SMEM (4 * 128 * KS * 2)   // 139264 bytes

__device__ __forceinline__ void mma16816(float* c, const uint32_t* a,
                                         uint32_t b0, uint32_t b1) {
    asm volatile(
        "mma.sync.aligned.m16n8k16.row.col.f32.f16.f16.f32 "
        "{%0,%1,%2,%3}, {%4,%5,%6,%7}, {%8,%9}, {%0,%1,%2,%3};"
        : "+f"(c[0]), "+f"(c[1]), "+f"(c[2]), "+f"(c[3])
        : "r"(a[0]), "r"(a[1]), "r"(a[2]), "r"(a[3]), "r"(b0), "r"(b1));
}

__global__ void __launch_bounds__(256) k_gemm(const float* __restrict__ A,
                                              const float* __restrict__ W,
                                              __half* __restrict__ C, int n) {
    extern __shared__ __half sh[];
    __half* Ah = sh;
    __half* Al = Ah + 128 * KS;
    __half* Wh = Al + 128 * KS;
    __half* Wl = Wh + 128 * KS;

    int tid = threadIdx.x;
    int row0 = blockIdx.x * 128;

    // stage A -> hi/lo fp16
    for (int idx = tid; idx < 128 * 128; idx += 256) {
        int r = idx >> 7, k = idx & 127;
        float x = (row0 + r < n) ? A[(size_t)(row0 + r) * 128 + k] : 0.f;
        __half h = __float2half_rn(x);
        __half l = __float2half_rn(x - __half2float(h));
        Ah[r * KS + k] = h;
        Al[r * KS + k] = l;
    }
    // stage W^T -> hi/lo fp16 (Wt[nn][k] = W[k][nn]; coalesced gmem reads)
    for (int idx = tid; idx < 128 * 128; idx += 256) {
        int k = idx >> 7, nn = idx & 127;
        float x = W[idx];
        __half h = __float2half_rn(x);
        __half l = __float2half_rn(x - __half2float(h));
        Wh[nn * KS + k] = h;
        Wl[nn * KS + k] = l;
    }
    __syncthreads();

    int wid = tid >> 5;
    int lane = tid & 31;
    int m0 = wid * 16;
    int gr = lane >> 2;         // 0..7
    int gc = (lane & 3) * 2;    // 0,2,4,6

    float c[16][4];
#pragma unroll
    for (int i = 0; i < 16; i++)
#pragma unroll
        for (int j = 0; j < 4; j++) c[i][j] = 0.f;

#pragma unroll
    for (int k0 = 0; k0 < 128; k0 += 16) {
        uint32_t ah[4], al[4];
        ah[0] = *(const uint32_t*)(Ah + (m0 + gr) * KS + k0 + gc);
        ah[1] = *(const uint32_t*)(Ah + (m0 + gr + 8) * KS + k0 + gc);
        ah[2] = *(const uint32_t*)(Ah + (m0 + gr) * KS + k0 + 8 + gc);
        ah[3] = *(const uint32_t*)(Ah + (m0 + gr + 8) * KS + k0 + 8 + gc);
        al[0] = *(const uint32_t*)(Al + (m0 + gr) * KS + k0 + gc);
        al[1] = *(const uint32_t*)(Al + (m0 + gr + 8) * KS + k0 + gc);
        al[2] = *(const uint32_t*)(Al + (m0 + gr) * KS + k0 + 8 + gc);
        al[3] = *(const uint32_t*)(Al + (m0 + gr + 8) * KS + k0 + 8 + gc);
#pragma unroll
        for (int n0 = 0; n0 < 16; n0++) {
            const __half* wh = Wh + (n0 * 8 + gr) * KS + k0 + gc;
            const __half* wl = Wl + (n0 * 8 + gr) * KS + k0 + gc;
            uint32_t bh0 = *(const uint32_t*)(wh);
            uint32_t bh1 = *(const uint32_t*)(wh + 8);
            uint32_t bl0 = *(const uint32_t*)(wl);
            uint32_t bl1 = *(const uint32_t*)(wl + 8);
            mma16816(c[n0], ah, bh0, bh1);
            mma16816(c[n0], ah, bl0, bl1);
            mma16816(c[n0], al, bh0, bh1);
        }
    }

    // epilogue: c0,c1 -> (row m0+gr, cols n0*8+gc..+1); c2,c3 -> row +8
    int rowa = row0 + m0 + gr;
    int rowb = rowa + 8;
#pragma unroll
    for (int n0 = 0; n0 < 16; n0++) {
        int col = n0 * 8 + gc;
        if (rowa < n) {
            __half2 h = __floats2half2_rn(c[n0][0], c[n0][1]);
            *(__half2*)(C + (size_t)rowa * D + col) = h;
        }
        if (rowb < n) {
            __half2 h = __floats2half2_rn(c[n0][2], c[n0][3]);
            *(__half2*)(C + (size_t)rowb * D + col) = h;
        }
    }
}

// ---------------- CSR gather-aggregate (half-warp per edge, 8-edge unroll) -----

__device__ __forceinline__ void acc8(float* acc, float w, uint4 v) {
    float2 f0 = __half22float2(*(__half2*)&v.x);
    float2 f1 = __half22float2(*(__half2*)&v.y);
    float2 f2 = __half22float2(*(__half2*)&v.z);
    float2 f3 = __half22float2(*(__half2*)&v.w);
    acc[0] += w * f0.x; acc[1] += w * f0.y;
    acc[2] += w * f1.x; acc[3] += w * f1.y;
    acc[4] += w * f2.x; acc[5] += w * f2.y;
    acc[6] += w * f3.x; acc[7] += w * f3.y;
}

__device__ __forceinline__ void agg_list_hw(const __half* __restrict__ h,
                                            const int2* __restrict__ eds,
                                            int j, int end,
                                            int half_id, int col8, float* acc) {
    for (; j + 7 < end; j += 8) {
        int2 e0 = __ldg(eds + j + half_id);
        int2 e1 = __ldg(eds + j + 2 + half_id);
        int2 e2 = __ldg(eds + j + 4 + half_id);
        int2 e3 = __ldg(eds + j + 6 + half_id);
        uint4 v0 = __ldg((const uint4*)(h + (size_t)e0.x * D) + col8);
        uint4 v1 = __ldg((const uint4*)(h + (size_t)e1.x * D) + col8);
        uint4 v2 = __ldg((const uint4*)(h + (size_t)e2.x * D) + col8);
        uint4 v3 = __ldg((const uint4*)(h + (size_t)e3.x * D) + col8);
        acc8(acc, __int_as_float(e0.y), v0);
        acc8(acc, __int_as_float(e1.y), v1);
        acc8(acc, __int_as_float(e2.y), v2);
        acc8(acc, __int_as_float(e3.y), v3);
    }
    if (j + 3 < end) {
        int2 e0 = __ldg(eds + j + half_id);
        int2 e1 = __ldg(eds + j + 2 + half_id);
        uint4 v0 = __ldg((const uint4*)(h + (size_t)e0.x * D) + col8);
        uint4 v1 = __ldg((const uint4*)(h + (size_t)e1.x * D) + col8);
        acc8(acc, __int_as_float(e0.y), v0);
        acc8(acc, __int_as_float(e1.y), v1);
        j += 4;
    }
    if (j + 1 < end) {
        int2 e0 = __ldg(eds + j + half_id);
        uint4 v0 = __ldg((const uint4*)(h + (size_t)e0.x * D) + col8);
        acc8(acc, __int_as_float(e0.y), v0);
        j += 2;
    }
    if (j < end && half_id == 0) {
        int2 e0 = __ldg(eds + j);
        uint4 v0 = __ldg((const uint4*)(h + (size_t)e0.x * D) + col8);
        acc8(acc, __int_as_float(e0.y), v0);
    }
}

template <bool RELU>
__global__ void __launch_bounds__(256) k_agg_user(
    const __half* __restrict__ h,
    const float* __restrict__ bF, const float* __restrict__ bV,
    float* __restrict__ outp) {
    int warp = (blockIdx.x * blockDim.x + threadIdx.x) >> 5;
    if (warp >= NU) return;
    int lane = threadIdx.x & 31;
    int half_id = lane >> 4;
    int col8 = lane & 15;

    float acc[8];
#pragma unroll
    for (int k = 0; k < 8; k++) acc[k] = 0.f;

    agg_list_hw(h, g_ec, g_off_c[warp], g_off_c[warp + 1], half_id, col8, acc);

#pragma unroll
    for (int k = 0; k < 8; k++)
        acc[k] += __shfl_down_sync(0xffffffff, acc[k], 16);

    if (half_id == 0) {
        float4 b10 = __ldg((const float4*)bF + col8 * 2);
        float4 b11 = __ldg((const float4*)bF + col8 * 2 + 1);
        float4 b20 = __ldg((const float4*)bV + col8 * 2);
        float4 b21 = __ldg((const float4*)bV + col8 * 2 + 1);
        float4 o0, o1;
        o0.x = acc[0] + 0.5f * (b10.x + b20.x);
        o0.y = acc[1] + 0.5f * (b10.y + b20.y);
        o0.z = acc[2] + 0.5f * (b10.z + b20.z);
        o0.w = acc[3] + 0.5f * (b10.w + b20.w);
        o1.x = acc[4] + 0.5f * (b11.x + b21.x);
        o1.y = acc[5] + 0.5f * (b11.y + b21.y);
        o1.z = acc[6] + 0.5f * (b11.z + b21.z);
        o1.w = acc[7] + 0.5f * (b11.w + b21.w);
        if (RELU) {
            o0.x = fmaxf(o0.x, 0.f); o0.y = fmaxf(o0.y, 0.f);
            o0.z = fmaxf(o0.z, 0.f); o0.w = fmaxf(o0.w, 0.f);
            o1.x = fmaxf(o1.x, 0.f); o1.y = fmaxf(o1.y, 0.f);
            o1.z = fmaxf(o1.z, 0.f); o1.w = fmaxf(o1.w, 0.f);
        }
        float4* orow = (float4*)(outp + (size_t)warp * D) + col8 * 2;
        orow[0] = o0;
        orow[1] = o1;
    }
}

template <bool RELU>
__global__ void __launch_bounds__(256) k_agg_item(
    const __half* __restrict__ h, const float* __restrict__ b,
    float* __restrict__ outp) {
    int warp = (blockIdx.x * blockDim.x + threadIdx.x) >> 5;
    if (warp >= NI) return;
    int lane = threadIdx.x & 31;
    int half_id = lane >> 4;
    int col8 = lane & 15;

    float acc[8];
#pragma unroll
    for (int k = 0; k < 8; k++) acc[k] = 0.f;

    agg_list_hw(h, g_er, g_off_r[warp], g_off_r[warp + 1], half_id, col8, acc);

#pragma unroll
    for (int k = 0; k < 8; k++)
        acc[k] += __shfl_down_sync(0xffffffff, acc[k], 16);

    if (half_id == 0) {
        float4 b0 = __ldg((const float4*)b + col8 * 2);
        float4 b1 = __ldg((const float4*)b + col8 * 2 + 1);
        float4 o0, o1;
        o0.x = acc[0] + b0.x; o0.y = acc[1] + b0.y;
        o0.z = acc[2] + b0.z; o0.w = acc[3] + b0.w;
        o1.x = acc[4] + b1.x; o1.y = acc[5] + b1.y;
        o1.z = acc[6] + b1.z; o1.w = acc[7] + b1.w;
        if (RELU) {
            o0.x = fmaxf(o0.x, 0.f); o0.y = fmaxf(o0.y, 0.f);
            o0.z = fmaxf(o0.z, 0.f); o0.w = fmaxf(o0.w, 0.f);
            o1.x = fmaxf(o1.x, 0.f); o1.y = fmaxf(o1.y, 0.f);
            o1.z = fmaxf(o1.z, 0.f); o1.w = fmaxf(o1.w, 0.f);
        }
        float4* orow = (float4*)(outp + (size_t)warp * D) + col8 * 2;
        orow[0] = o0;
        orow[1] = o1;
    }
}

// ---------------- host driver --------------------------------------------------

extern "C" void kernel_launch(void* const* d_in, const int* in_sizes, int n_in,
                              void* d_out, int out_size) {
    const float* x_user = (const float*)d_in[0];
    const float* x_item = (const float*)d_in[1];
    const int* f_src = (const int*)d_in[2];
    const int* f_dst = (const int*)d_in[3];
    const int* r_src = (const int*)d_in[4];
    const int* r_dst = (const int*)d_in[5];
    const int* v_src = (const int*)d_in[6];
    const int* v_dst = (const int*)d_in[7];

    const float *W1f, *W1r, *W1v, *W2f, *W2r, *W2v;
    const float *b1f, *b1r, *b1v, *b2f, *b2r, *b2v;
    if (in_sizes[9] == 128 * 128) {
        W1f = (const float*)d_in[8];  W1r = (const float*)d_in[9];  W1v = (const float*)d_in[10];
        W2f = (const float*)d_in[11]; W2r = (const float*)d_in[12]; W2v = (const float*)d_in[13];
        b1f = (const float*)d_in[14]; b1r = (const float*)d_in[15]; b1v = (const float*)d_in[16];
        b2f = (const float*)d_in[17]; b2r = (const float*)d_in[18]; b2v = (const float*)d_in[19];
    } else {
        W1f = (const float*)d_in[8];  b1f = (const float*)d_in[9];
        W1r = (const float*)d_in[10]; b1r = (const float*)d_in[11];
        W1v = (const float*)d_in[12]; b1v = (const float*)d_in[13];
        W2f = (const float*)d_in[14]; b2f = (const float*)d_in[15];
        W2r = (const float*)d_in[16]; b2r = (const float*)d_in[17];
        W2v = (const float*)d_in[18]; b2v = (const float*)d_in[19];
    }
    float* out = (float*)d_out;

    __half *hc1, *hc2, *hu2, *hu2b;
    float *u, *it;
    cudaGetSymbolAddress((void**)&hc1, g_hc1);
    cudaGetSymbolAddress((void**)&hc2, g_hc2);
    cudaGetSymbolAddress((void**)&hu2, g_hu2);
    cudaGetSymbolAddress((void**)&hu2b, g_hu2b);
    cudaGetSymbolAddress((void**)&u,  g_u);
    cudaGetSymbolAddress((void**)&it, g_it);
    __half* hu1 = hc1;
    __half* hi  = hc1 + (size_t)NU * D;
    __half* hu1b = hc2;
    __half* hib  = hc2 + (size_t)NU * D;

    static cudaStream_t s1 = 0, s2 = 0;
    static cudaEvent_t evFork = 0, evCSR = 0, evL1 = 0, evHu2 = 0, evU = 0,
                       evItG = 0, evHu2b = 0, evEnd = 0;
    if (s1 == 0) {
        cudaStreamCreateWithFlags(&s1, cudaStreamNonBlocking);
        cudaStreamCreateWithFlags(&s2, cudaStreamNonBlocking);
        cudaEventCreateWithFlags(&evFork, cudaEventDisableTiming);
        cudaEventCreateWithFlags(&evCSR,  cudaEventDisableTiming);
        cudaEventCreateWithFlags(&evL1,   cudaEventDisableTiming);
        cudaEventCreateWithFlags(&evHu2,  cudaEventDisableTiming);
        cudaEventCreateWithFlags(&evU,    cudaEventDisableTiming);
        cudaEventCreateWithFlags(&evItG,  cudaEventDisableTiming);
        cudaEventCreateWithFlags(&evHu2b, cudaEventDisableTiming);
        cudaEventCreateWithFlags(&evEnd,  cudaEventDisableTiming);
    }

    const int TB = 256;
    cudaFuncSetAttribute(k_gemm, cudaFuncAttributeMaxDynamicSharedMemorySize, GEMM_SMEM);

    int gNU   = (NU + TB - 1) / TB;
    int gAggU = (NU * 32 + TB - 1) / TB;
    int gAggI = (NI * 32 + TB - 1) / TB;
    int gGU   = (NU + 127) / 128;
    int gGI   = (NI + 127) / 128;
    int nbU = (NU + 1023) / 1024;

    dim3 gEdge3((NE + TB - 1) / TB, 3);
    dim3 gScan1(nbU, 2);
    dim3 gScan3((NU + 1 + TB - 1) / TB, 2);

    // ---- s1: CSR build (overlaps s0 L1 GEMMs) --------------------------------
    cudaEventRecord(evFork, 0);
    cudaStreamWaitEvent(s1, evFork, 0);
    cudaStreamWaitEvent(s2, evFork, 0);
    k_zero_hists<<<gNU, TB, 0, s1>>>();
    k_hist3<<<gEdge3, TB, 0, s1>>>(f_src, f_dst, r_src, r_dst, v_src, v_dst);
    k_inv_all<<<gNU, TB, 0, s1>>>();
    k_scan1<<<gScan1, 1024, 0, s1>>>();
    k_scan2<<<2, 1024, 0, s1>>>();
    k_scan3<<<gScan3, TB, 0, s1>>>();
    k_fill3<<<gEdge3, TB, 0, s1>>>(f_src, f_dst, r_src, r_dst, v_src, v_dst);
    cudaEventRecord(evCSR, s1);

    // ---- s0: user-critical L1 GEMMs (hu1, hi) ----------------------------------
    k_gemm<<<gGU, 256, GEMM_SMEM>>>(x_user, W1f, hu1, NU);
    k_gemm<<<gGI, 256, GEMM_SMEM>>>(x_item, W1v, hi,  NI);
    cudaEventRecord(evL1, 0);

    // ---- s2: hu2 GEMM overlaps agg_user1 ----------------------------------------
    cudaStreamWaitEvent(s2, evL1, 0);
    k_gemm<<<gGU, 256, GEMM_SMEM, s2>>>(x_user, W1r, hu2, NU);
    cudaEventRecord(evHu2, s2);

    // ---- s0: user chain: agg1 -> W2f ---------------------------------------------
    cudaStreamWaitEvent(0, evCSR, 0);
    k_agg_user<true><<<gAggU, TB>>>(hc1, b1f, b1v, u);
    cudaEventRecord(evU, 0);
    k_gemm<<<gGU, 256, GEMM_SMEM>>>(u, W2f, hu1b, NU);

    // ---- s1: item pipeline ---------------------------------------------------------
    cudaStreamWaitEvent(s1, evHu2, 0);
    k_agg_item<true><<<gAggI, TB, 0, s1>>>(hu2, b1r, it);
    k_gemm<<<gGI, 256, GEMM_SMEM, s1>>>(it, W2v, hib, NI);
    cudaEventRecord(evItG, s1);

    // ---- s2: W2r overlaps W2f/agg_user2 ---------------------------------------------
    cudaStreamWaitEvent(s2, evU, 0);
    k_gemm<<<gGU, 256, GEMM_SMEM, s2>>>(u, W2r, hu2b, NU);
    cudaEventRecord(evHu2b, s2);

    // ---- s1: final item agg -----------------------------------------------------------
    cudaStreamWaitEvent(s1, evHu2b, 0);
    k_agg_item<false><<<gAggI, TB, 0, s1>>>(hu2b, b2r, out + (size_t)NU * D);
    cudaEventRecord(evEnd, s1);

    // ---- s0: final user agg --------------------------------------------------------------
    cudaStreamWaitEvent(0, evItG, 0);
    k_agg_user<false><<<gAggU, TB>>>(hc2, b2f, b2v, out);
    cudaStreamWaitEvent(0, evEnd, 0);  // join
}

// round 16
// speedup vs baseline: 1.1053x; 1.1053x over previous
#include <cuda_runtime.h>
#include <cuda_fp16.h>

#define NU 100000
#define NI 50000
#define NE 1600000
#define D  128

// ---------------- scratch (device globals) ----------------------------------
__device__ int g_h_fs[NU];
__device__ int g_h_fd[NU];
__device__ int g_h_rs[NU];
__device__ int g_h_rd[NI];
__device__ int g_h_vs[NI];
__device__ int g_h_vd[NU];

// combined user CSR (follows + rev, fully folded weights), item CSR (rates)
__device__ int   g_off_c[NU + 1];
__device__ int   g_off_r[NI + 1];
__device__ int   g_pos_c[NU];
__device__ int   g_pos_r[NI];
__device__ int2  g_ec[2 * NE];   // {src' (rev: NU+src), w_bits = full coeff}
__device__ int2  g_er[NE];
__device__ int   g_bsum[2][1024];

// layer h-buffers: user rows [0,NU), item rows [NU,NU+NI) contiguous
__device__ __half g_hc1[(size_t)(NU + NI) * D];
__device__ __half g_hc2[(size_t)(NU + NI) * D];
__device__ __half g_hu2 [(size_t)NU * D];
__device__ __half g_hu2b[(size_t)NU * D];
__device__ float  g_u  [(size_t)NU * D];
__device__ float  g_it [(size_t)NI * D];

// ---------------- setup kernels ----------------------------------------------

__global__ void k_zero_hists() {
    int i = blockIdx.x * blockDim.x + threadIdx.x;
    if (i < NU) { g_h_fs[i] = 0; g_h_fd[i] = 0; g_h_rs[i] = 0; g_h_vd[i] = 0; }
    if (i < NI) { g_h_rd[i] = 0; g_h_vs[i] = 0; }
}

__global__ void k_hist3(const int* __restrict__ fs, const int* __restrict__ fd,
                        const int* __restrict__ rs, const int* __restrict__ rd,
                        const int* __restrict__ vs, const int* __restrict__ vd) {
    int e = blockIdx.x * blockDim.x + threadIdx.x;
    if (e >= NE) return;
    if (blockIdx.y == 0) {
        atomicAdd(&g_h_fs[fs[e]], 1);
        atomicAdd(&g_h_fd[fd[e]], 1);
    } else if (blockIdx.y == 1) {
        atomicAdd(&g_h_rs[rs[e]], 1);
        atomicAdd(&g_h_rd[rd[e]], 1);
    } else {
        atomicAdd(&g_h_vs[vs[e]], 1);
        atomicAdd(&g_h_vd[vd[e]], 1);
    }
}

__device__ __forceinline__ float invsq(int x) {
    return x > 0 ? rsqrtf((float)x) : 0.f;
}

// ---------------- exclusive scan (2 arrays per launch via blockIdx.y) ---------

__global__ void k_scan1() {
    __shared__ int s[1024];
    int tid = threadIdx.x;
    int i = blockIdx.x * 1024 + tid;
    int v;
    int* outp; int n;
    if (blockIdx.y == 0) {
        n = NU; outp = g_off_c;
        v = (i < n) ? (g_h_fd[i] + g_h_vd[i]) : 0;
    } else {
        n = NI; outp = g_off_r;
        v = (i < n) ? g_h_rd[i] : 0;
    }
    s[tid] = v;
    __syncthreads();
#pragma unroll
    for (int o = 1; o < 1024; o <<= 1) {
        int t = (tid >= o) ? s[tid - o] : 0;
        __syncthreads();
        s[tid] += t;
        __syncthreads();
    }
    if (i < n) outp[i] = s[tid] - v;
    if (tid == 1023) g_bsum[blockIdx.y][blockIdx.x] = s[1023];
}

__global__ void k_scan2() {
    __shared__ int s[1024];
    int nb = (blockIdx.x == 1) ? (NI + 1023) / 1024 : (NU + 1023) / 1024;
    int tid = threadIdx.x;
    int v = (tid < nb) ? g_bsum[blockIdx.x][tid] : 0;
    s[tid] = v;
    __syncthreads();
#pragma unroll
    for (int o = 1; o < 1024; o <<= 1) {
        int t = (tid >= o) ? s[tid - o] : 0;
        __syncthreads();
        s[tid] += t;
        __syncthreads();
    }
    if (tid < nb) g_bsum[blockIdx.x][tid] = s[tid] - v;
}

__global__ void k_scan3() {
    int* outp; int* pos; int n; int total;
    if (blockIdx.y == 0) { outp = g_off_c; pos = g_pos_c; n = NU; total = 2 * NE; }
    else                 { outp = g_off_r; pos = g_pos_r; n = NI; total = NE; }
    int i = blockIdx.x * blockDim.x + threadIdx.x;
    if (i < n) {
        int v = outp[i] + g_bsum[blockIdx.y][i >> 10];
        outp[i] = v;
        pos[i] = v;
    } else if (i == n) {
        outp[n] = total;
    }
}

// fill: inv-sqrt norms computed on the fly (2 MUFU/edge; removes k_inv_all)
__global__ void k_fill3(const int* __restrict__ fs, const int* __restrict__ fd,
                        const int* __restrict__ rs, const int* __restrict__ rd,
                        const int* __restrict__ vs, const int* __restrict__ vd) {
    int e = blockIdx.x * blockDim.x + threadIdx.x;
    if (e >= NE) return;
    if (blockIdx.y == 0) {            // follows: user->user
        int s = fs[e], d = fd[e];
        float w = 0.5f * invsq(g_h_fs[s]) * invsq(g_h_fd[d]);
        int p = atomicAdd(&g_pos_c[d], 1);
        g_ec[p] = make_int2(s, __float_as_int(w));
    } else if (blockIdx.y == 1) {     // rates: user->item
        int s = rs[e], d = rd[e];
        float w = invsq(g_h_rs[s]) * invsq(g_h_rd[d]);
        int p = atomicAdd(&g_pos_r[d], 1);
        g_er[p] = make_int2(s, __float_as_int(w));
    } else {                          // rev: item->user (src offset by NU)
        int s = vs[e], d = vd[e];
        float w = 0.5f * invsq(g_h_vs[s]) * invsq(g_h_vd[d]);
        int p = atomicAdd(&g_pos_c[d], 1);
        g_ec[p] = make_int2(NU + s, __float_as_int(w));
    }
}

// ---------------- GEMM core (FFMA2 row-pair, champion kernel) ------------------

#define GEMM_SMEM ((128 * 128 + 128 * 64) * 4)  // W 64KB + At 32KB
#define NBU ((NU + 63) / 64)   // 1563 user blocks in fused L1 grid
#define NBI ((NI + 63) / 64)   // 782 item blocks

__device__ __forceinline__ void gemm_body(const float* __restrict__ A,
                                          const float* __restrict__ W,
                                          __half* __restrict__ C,
                                          int row0, int bound, float* sm,
                                          int tid) {
    float* Ws = sm;               // [128][128]
    float* At = sm + 128 * 128;   // [128 k][64 row]

    for (int i = tid; i < 128 * 32; i += 256)
        ((float4*)Ws)[i] = ((const float4*)W)[i];

    for (int i = tid; i < 64 * 32; i += 256) {
        int c = i >> 6;
        int r = i & 63;
        int row = row0 + r;
        float4 v = (row < bound) ? ((const float4*)A)[(size_t)row * 32 + c]
                                 : make_float4(0.f, 0.f, 0.f, 0.f);
        At[(4 * c + 0) * 64 + r] = v.x;
        At[(4 * c + 1) * 64 + r] = v.y;
        At[(4 * c + 2) * 64 + r] = v.z;
        At[(4 * c + 3) * 64 + r] = v.w;
    }
    __syncthreads();

    int ty = tid >> 5;
    int tx = tid & 31;

    unsigned long long acc[4][4];
#pragma unroll
    for (int p = 0; p < 4; p++)
#pragma unroll
        for (int c = 0; c < 4; c++) acc[p][c] = 0ull;

    const float* at = At + ty * 8;
#pragma unroll 8
    for (int k = 0; k < 128; k++) {
        ulonglong2 a01 = *(const ulonglong2*)(at + k * 64);
        ulonglong2 a23 = *(const ulonglong2*)(at + k * 64 + 4);
        float4 wv = ((const float4*)(Ws + k * 128))[tx];
        unsigned long long wb0, wb1, wb2, wb3;
        asm("mov.b64 %0, {%1, %1};" : "=l"(wb0) : "f"(wv.x));
        asm("mov.b64 %0, {%1, %1};" : "=l"(wb1) : "f"(wv.y));
        asm("mov.b64 %0, {%1, %1};" : "=l"(wb2) : "f"(wv.z));
        asm("mov.b64 %0, {%1, %1};" : "=l"(wb3) : "f"(wv.w));
        asm("fma.rn.f32x2 %0, %1, %2, %0;" : "+l"(acc[0][0]) : "l"(a01.x), "l"(wb0));
        asm("fma.rn.f32x2 %0, %1, %2, %0;" : "+l"(acc[0][1]) : "l"(a01.x), "l"(wb1));
        asm("fma.rn.f32x2 %0, %1, %2, %0;" : "+l"(acc[0][2]) : "l"(a01.x), "l"(wb2));
        asm("fma.rn.f32x2 %0, %1, %2, %0;" : "+l"(acc[0][3]) : "l"(a01.x), "l"(wb3));
        asm("fma.rn.f32x2 %0, %1, %2, %0;" : "+l"(acc[1][0]) : "l"(a01.y), "l"(wb0));
        asm("fma.rn.f32x2 %0, %1, %2, %0;" : "+l"(acc[1][1]) : "l"(a01.y), "l"(wb1));
        asm("fma.rn.f32x2 %0, %1, %2, %0;" : "+l"(acc[1][2]) : "l"(a01.y), "l"(wb2));
        asm("fma.rn.f32x2 %0, %1, %2, %0;" : "+l"(acc[1][3]) : "l"(a01.y), "l"(wb3));
        asm("fma.rn.f32x2 %0, %1, %2, %0;" : "+l"(acc[2][0]) : "l"(a23.x), "l"(wb0));
        asm("fma.rn.f32x2 %0, %1, %2, %0;" : "+l"(acc[2][1]) : "l"(a23.x), "l"(wb1));
        asm("fma.rn.f32x2 %0, %1, %2, %0;" : "+l"(acc[2][2]) : "l"(a23.x), "l"(wb2));
        asm("fma.rn.f32x2 %0, %1, %2, %0;" : "+l"(acc[2][3]) : "l"(a23.x), "l"(wb3));
        asm("fma.rn.f32x2 %0, %1, %2, %0;" : "+l"(acc[3][0]) : "l"(a23.y), "l"(wb0));
        asm("fma.rn.f32x2 %0, %1, %2, %0;" : "+l"(acc[3][1]) : "l"(a23.y), "l"(wb1));
        asm("fma.rn.f32x2 %0, %1, %2, %0;" : "+l"(acc[3][2]) : "l"(a23.y), "l"(wb2));
        asm("fma.rn.f32x2 %0, %1, %2, %0;" : "+l"(acc[3][3]) : "l"(a23.y), "l"(wb3));
    }

#pragma unroll
    for (int p = 0; p < 4; p++) {
        float e0, o0, e1, o1, e2, o2, e3, o3;
        asm("mov.b64 {%0, %1}, %2;" : "=f"(e0), "=f"(o0) : "l"(acc[p][0]));
        asm("mov.b64 {%0, %1}, %2;" : "=f"(e1), "=f"(o1) : "l"(acc[p][1]));
        asm("mov.b64 {%0, %1}, %2;" : "=f"(e2), "=f"(o2) : "l"(acc[p][2]));
        asm("mov.b64 {%0, %1}, %2;" : "=f"(e3), "=f"(o3) : "l"(acc[p][3]));
        int row = row0 + ty * 8 + 2 * p;
        if (row < bound) {
            __half2 h0 = __floats2half2_rn(e0, e1);
            __half2 h1 = __floats2half2_rn(e2, e3);
            *(uint2*)(C + (size_t)row * D + tx * 4) =
                make_uint2(*(unsigned*)&h0, *(unsigned*)&h1);
        }
        if (row + 1 < bound) {
            __half2 h0 = __floats2half2_rn(o0, o1);
            __half2 h1 = __floats2half2_rn(o2, o3);
            *(uint2*)(C + (size_t)(row + 1) * D + tx * 4) =
                make_uint2(*(unsigned*)&h0, *(unsigned*)&h1);
        }
    }
}

__global__ void __launch_bounds__(256) k_gemm(const float* __restrict__ A,
                                              const float* __restrict__ W,
                                              __half* __restrict__ C, int n) {
    extern __shared__ float sm[];
    gemm_body(A, W, C, blockIdx.x * 64, n, sm, threadIdx.x);
}

// fused layer-1 GEMM: user region (x_user @ W1f) + item region (x_item @ W1v)
// writing the contiguous hc1 buffer in one launch.
__global__ void __launch_bounds__(256) k_gemm_l1(const float* __restrict__ xu,
                                                 const float* __restrict__ Wf,
                                                 const float* __restrict__ xi,
                                                 const float* __restrict__ Wv,
                                                 __half* __restrict__ C) {
    extern __shared__ float sm[];
    if (blockIdx.x < NBU) {
        gemm_body(xu, Wf, C, blockIdx.x * 64, NU, sm, threadIdx.x);
    } else {
        // item region: rows are offset by NU in the output buffer
        gemm_body(xi, Wv, C + (size_t)NU * D, (blockIdx.x - NBU) * 64, NI,
                  sm, threadIdx.x);
    }
}

// ---------------- CSR gather-aggregate (half-warp per edge, 8-edge unroll) -----

__device__ __forceinline__ void acc8(float* acc, float w, uint4 v) {
    float2 f0 = __half22float2(*(__half2*)&v.x);
    float2 f1 = __half22float2(*(__half2*)&v.y);
    float2 f2 = __half22float2(*(__half2*)&v.z);
    float2 f3 = __half22float2(*(__half2*)&v.w);
    acc[0] += w * f0.x; acc[1] += w * f0.y;
    acc[2] += w * f1.x; acc[3] += w * f1.y;
    acc[4] += w * f2.x; acc[5] += w * f2.y;
    acc[6] += w * f3.x; acc[7] += w * f3.y;
}

__device__ __forceinline__ void agg_list_hw(const __half* __restrict__ h,
                                            const int2* __restrict__ eds,
                                            int j, int end,
                                            int half_id, int col8, float* acc) {
    for (; j + 7 < end; j += 8) {
        int2 e0 = __ldg(eds + j + half_id);
        int2 e1 = __ldg(eds + j + 2 + half_id);
        int2 e2 = __ldg(eds + j + 4 + half_id);
        int2 e3 = __ldg(eds + j + 6 + half_id);
        uint4 v0 = __ldg((const uint4*)(h + (size_t)e0.x * D) + col8);
        uint4 v1 = __ldg((const uint4*)(h + (size_t)e1.x * D) + col8);
        uint4 v2 = __ldg((const uint4*)(h + (size_t)e2.x * D) + col8);
        uint4 v3 = __ldg((const uint4*)(h + (size_t)e3.x * D) + col8);
        acc8(acc, __int_as_float(e0.y), v0);
        acc8(acc, __int_as_float(e1.y), v1);
        acc8(acc, __int_as_float(e2.y), v2);
        acc8(acc, __int_as_float(e3.y), v3);
    }
    if (j + 3 < end) {
        int2 e0 = __ldg(eds + j + half_id);
        int2 e1 = __ldg(eds + j + 2 + half_id);
        uint4 v0 = __ldg((const uint4*)(h + (size_t)e0.x * D) + col8);
        uint4 v1 = __ldg((const uint4*)(h + (size_t)e1.x * D) + col8);
        acc8(acc, __int_as_float(e0.y), v0);
        acc8(acc, __int_as_float(e1.y), v1);
        j += 4;
    }
    if (j + 1 < end) {
        int2 e0 = __ldg(eds + j + half_id);
        uint4 v0 = __ldg((const uint4*)(h + (size_t)e0.x * D) + col8);
        acc8(acc, __int_as_float(e0.y), v0);
        j += 2;
    }
    if (j < end && half_id == 0) {
        int2 e0 = __ldg(eds + j);
        uint4 v0 = __ldg((const uint4*)(h + (size_t)e0.x * D) + col8);
        acc8(acc, __int_as_float(e0.y), v0);
    }
}

template <bool RELU>
__global__ void __launch_bounds__(256) k_agg_user(
    const __half* __restrict__ h,
    const float* __restrict__ bF, const float* __restrict__ bV,
    float* __restrict__ outp) {
    int warp = (blockIdx.x * blockDim.x + threadIdx.x) >> 5;
    if (warp >= NU) return;
    int lane = threadIdx.x & 31;
    int half_id = lane >> 4;
    int col8 = lane & 15;

    float acc[8];
#pragma unroll
    for (int k = 0; k < 8; k++) acc[k] = 0.f;

    agg_list_hw(h, g_ec, g_off_c[warp], g_off_c[warp + 1], half_id, col8, acc);

#pragma unroll
    for (int k = 0; k < 8; k++)
        acc[k] += __shfl_down_sync(0xffffffff, acc[k], 16);

    if (half_id == 0) {
        float4 b10 = __ldg((const float4*)bF + col8 * 2);
        float4 b11 = __ldg((const float4*)bF + col8 * 2 + 1);
        float4 b20 = __ldg((const float4*)bV + col8 * 2);
        float4 b21 = __ldg((const float4*)bV + col8 * 2 + 1);
        float4 o0, o1;
        o0.x = acc[0] + 0.5f * (b10.x + b20.x);
        o0.y = acc[1] + 0.5f * (b10.y + b20.y);
        o0.z = acc[2] + 0.5f * (b10.z + b20.z);
        o0.w = acc[3] + 0.5f * (b10.w + b20.w);
        o1.x = acc[4] + 0.5f * (b11.x + b21.x);
        o1.y = acc[5] + 0.5f * (b11.y + b21.y);
        o1.z = acc[6] + 0.5f * (b11.z + b21.z);
        o1.w = acc[7] + 0.5f * (b11.w + b21.w);
        if (RELU) {
            o0.x = fmaxf(o0.x, 0.f); o0.y = fmaxf(o0.y, 0.f);
            o0.z = fmaxf(o0.z, 0.f); o0.w = fmaxf(o0.w, 0.f);
            o1.x = fmaxf(o1.x, 0.f); o1.y = fmaxf(o1.y, 0.f);
            o1.z = fmaxf(o1.z, 0.f); o1.w = fmaxf(o1.w, 0.f);
        }
        float4* orow = (float4*)(outp + (size_t)warp * D) + col8 * 2;
        orow[0] = o0;
        orow[1] = o1;
    }
}

template <bool RELU>
__global__ void __launch_bounds__(256) k_agg_item(
    const __half* __restrict__ h, const float* __restrict__ b,
    float* __restrict__ outp) {
    int warp = (blockIdx.x * blockDim.x + threadIdx.x) >> 5;
    if (warp >= NI) return;
    int lane = threadIdx.x & 31;
    int half_id = lane >> 4;
    int col8 = lane & 15;

    float acc[8];
#pragma unroll
    for (int k = 0; k < 8; k++) acc[k] = 0.f;

    agg_list_hw(h, g_er, g_off_r[warp], g_off_r[warp + 1], half_id, col8, acc);

#pragma unroll
    for (int k = 0; k < 8; k++)
        acc[k] += __shfl_down_sync(0xffffffff, acc[k], 16);

    if (half_id == 0) {
        float4 b0 = __ldg((const float4*)b + col8 * 2);
        float4 b1 = __ldg((const float4*)b + col8 * 2 + 1);
        float4 o0, o1;
        o0.x = acc[0] + b0.x; o0.y = acc[1] + b0.y;
        o0.z = acc[2] + b0.z; o0.w = acc[3] + b0.w;
        o1.x = acc[4] + b1.x; o1.y = acc[5] + b1.y;
        o1.z = acc[6] + b1.z; o1.w = acc[7] + b1.w;
        if (RELU) {
            o0.x = fmaxf(o0.x, 0.f); o0.y = fmaxf(o0.y, 0.f);
            o0.z = fmaxf(o0.z, 0.f); o0.w = fmaxf(o0.w, 0.f);
            o1.x = fmaxf(o1.x, 0.f); o1.y = fmaxf(o1.y, 0.f);
            o1.z = fmaxf(o1.z, 0.f); o1.w = fmaxf(o1.w, 0.f);
        }
        float4* orow = (float4*)(outp + (size_t)warp * D) + col8 * 2;
        orow[0] = o0;
        orow[1] = o1;
    }
}

// ---------------- host driver --------------------------------------------------

extern "C" void kernel_launch(void* const* d_in, const int* in_sizes, int n_in,
                              void* d_out, int out_size) {
    const float* x_user = (const float*)d_in[0];
    const float* x_item = (const float*)d_in[1];
    const int* f_src = (const int*)d_in[2];
    const int* f_dst = (const int*)d_in[3];
    const int* r_src = (const int*)d_in[4];
    const int* r_dst = (const int*)d_in[5];
    const int* v_src = (const int*)d_in[6];
    const int* v_dst = (const int*)d_in[7];

    const float *W1f, *W1r, *W1v, *W2f, *W2r, *W2v;
    const float *b1f, *b1r, *b1v, *b2f, *b2r, *b2v;
    if (in_sizes[9] == 128 * 128) {
        W1f = (const float*)d_in[8];  W1r = (const float*)d_in[9];  W1v = (const float*)d_in[10];
        W2f = (const float*)d_in[11]; W2r = (const float*)d_in[12]; W2v = (const float*)d_in[13];
        b1f = (const float*)d_in[14]; b1r = (const float*)d_in[15]; b1v = (const float*)d_in[16];
        b2f = (const float*)d_in[17]; b2r = (const float*)d_in[18]; b2v = (const float*)d_in[19];
    } else {
        W1f = (const float*)d_in[8];  b1f = (const float*)d_in[9];
        W1r = (const float*)d_in[10]; b1r = (const float*)d_in[11];
        W1v = (const float*)d_in[12]; b1v = (const float*)d_in[13];
        W2f = (const float*)d_in[14]; b2f = (const float*)d_in[15];
        W2r = (const float*)d_in[16]; b2r = (const float*)d_in[17];
        W2v = (const float*)d_in[18]; b2v = (const float*)d_in[19];
    }
    float* out = (float*)d_out;

    __half *hc1, *hc2, *hu2, *hu2b;
    float *u, *it;
    cudaGetSymbolAddress((void**)&hc1, g_hc1);
    cudaGetSymbolAddress((void**)&hc2, g_hc2);
    cudaGetSymbolAddress((void**)&hu2, g_hu2);
    cudaGetSymbolAddress((void**)&hu2b, g_hu2b);
    cudaGetSymbolAddress((void**)&u,  g_u);
    cudaGetSymbolAddress((void**)&it, g_it);
    __half* hu1b = hc2;
    __half* hib  = hc2 + (size_t)NU * D;

    static cudaStream_t s1 = 0, s2 = 0;
    static cudaEvent_t evFork = 0, evCSR = 0, evL1 = 0, evHu2 = 0, evU = 0,
                       evItG = 0, evHu2b = 0, evEnd = 0;
    if (s1 == 0) {
        cudaStreamCreateWithFlags(&s1, cudaStreamNonBlocking);
        cudaStreamCreateWithFlags(&s2, cudaStreamNonBlocking);
        cudaEventCreateWithFlags(&evFork, cudaEventDisableTiming);
        cudaEventCreateWithFlags(&evCSR,  cudaEventDisableTiming);
        cudaEventCreateWithFlags(&evL1,   cudaEventDisableTiming);
        cudaEventCreateWithFlags(&evHu2,  cudaEventDisableTiming);
        cudaEventCreateWithFlags(&evU,    cudaEventDisableTiming);
        cudaEventCreateWithFlags(&evItG,  cudaEventDisableTiming);
        cudaEventCreateWithFlags(&evHu2b, cudaEventDisableTiming);
        cudaEventCreateWithFlags(&evEnd,  cudaEventDisableTiming);
    }

    const int TB = 256;
    cudaFuncSetAttribute(k_gemm, cudaFuncAttributeMaxDynamicSharedMemorySize, GEMM_SMEM);
    cudaFuncSetAttribute(k_gemm_l1, cudaFuncAttributeMaxDynamicSharedMemorySize, GEMM_SMEM);

    int gNU   = (NU + TB - 1) / TB;
    int gAggU = (NU * 32 + TB - 1) / TB;
    int gAggI = (NI * 32 + TB - 1) / TB;
    int nbU = (NU + 1023) / 1024;

    dim3 gEdge3((NE + TB - 1) / TB, 3);
    dim3 gScan1(nbU, 2);
    dim3 gScan3((NU + 1 + TB - 1) / TB, 2);

    // ---- s1: CSR build (overlaps s0 L1 GEMMs) --------------------------------
    cudaEventRecord(evFork, 0);
    cudaStreamWaitEvent(s1, evFork, 0);
    cudaStreamWaitEvent(s2, evFork, 0);
    k_zero_hists<<<gNU, TB, 0, s1>>>();
    k_hist3<<<gEdge3, TB, 0, s1>>>(f_src, f_dst, r_src, r_dst, v_src, v_dst);
    k_scan1<<<gScan1, 1024, 0, s1>>>();
    k_scan2<<<2, 1024, 0, s1>>>();
    k_scan3<<<gScan3, TB, 0, s1>>>();
    k_fill3<<<gEdge3, TB, 0, s1>>>(f_src, f_dst, r_src, r_dst, v_src, v_dst);
    cudaEventRecord(evCSR, s1);

    // ---- s0: fused user-critical L1 GEMM (hu1 + hi in one launch) --------------
    k_gemm_l1<<<NBU + NBI, 256, GEMM_SMEM>>>(x_user, W1f, x_item, W1v, hc1);
    cudaEventRecord(evL1, 0);

    // ---- s2: hu2 GEMM overlaps agg_user1 ----------------------------------------
    cudaStreamWaitEvent(s2, evL1, 0);
    k_gemm<<<(NU + 63) / 64, 256, GEMM_SMEM, s2>>>(x_user, W1r, hu2, NU);
    cudaEventRecord(evHu2, s2);

    // ---- s0: user chain: agg1 -> W2f ---------------------------------------------
    cudaStreamWaitEvent(0, evCSR, 0);
    k_agg_user<true><<<gAggU, TB>>>(hc1, b1f, b1v, u);
    cudaEventRecord(evU, 0);
    k_gemm<<<(NU + 63) / 64, 256, GEMM_SMEM>>>(u, W2f, hu1b, NU);

    // ---- s1: item pipeline ---------------------------------------------------------
    cudaStreamWaitEvent(s1, evHu2, 0);
    k_agg_item<true><<<gAggI, TB, 0, s1>>>(hu2, b1r, it);
    k_gemm<<<(NI + 63) / 64, 256, GEMM_SMEM, s1>>>(it, W2v, hib, NI);
    cudaEventRecord(evItG, s1);

    // ---- s2: W2r overlaps W2f/agg_user2 ---------------------------------------------
    cudaStreamWaitEvent(s2, evU, 0);
    k_gemm<<<(NU + 63) / 64, 256, GEMM_SMEM, s2>>>(u, W2r, hu2b, NU);
    cudaEventRecord(evHu2b, s2);

    // ---- s1: final item agg -----------------------------------------------------------
    cudaStreamWaitEvent(s1, evHu2b, 0);
    k_agg_item<false><<<gAggI, TB, 0, s1>>>(hu2b, b2r, out + (size_t)NU * D);
    cudaEventRecord(evEnd, s1);

    // ---- s0: final user agg --------------------------------------------------------------
    cudaStreamWaitEvent(0, evItG, 0);
    k_agg_user<false><<<gAggU, TB>>>(hc2, b2f, b2v, out);
    cudaStreamWaitEvent(0, evEnd, 0);  // join
}